// round 3
// baseline (speedup 1.0000x reference)
#include <cuda_runtime.h>

#define B_ 4
#define T_ 128
#define S_ 512
#define D_ 512

// Scratch (allocation-free rule: __device__ globals)
__device__ __align__(16) float g_wq[B_ * T_ * D_];        // 1 MB
__device__ __align__(16) float g_uh[B_ * S_ * D_];        // 4 MB
__device__ __align__(16) float g_concat[B_ * T_ * 2 * D_];// 2 MB

__device__ __forceinline__ float fast_tanh(float x) {
    float y;
    asm("tanh.approx.f32 %0, %1;" : "=f"(y) : "f"(x));
    return y;
}

// ---------------------------------------------------------------------------
// NT GEMM: C[m,n] = sum_k A[m,k] * W[n,k] (+ bias[n])
// A: M x K row-major, W: N x K row-major.
// Tile: BM=32, BN=64, BK=16. 128 threads, 4x4 microtile per thread.
// ---------------------------------------------------------------------------
__global__ void gemm_nt_kernel(const float* __restrict__ A,
                               const float* __restrict__ W,
                               const float* __restrict__ bias,
                               float* __restrict__ C,
                               int M, int N, int K)
{
    __shared__ float As[16][32];   // [k][m]
    __shared__ float Ws[16][64];   // [k][n]

    const int tid = threadIdx.x;
    const int tx = tid & 15;       // n direction (16)
    const int ty = tid >> 4;       // m direction (8)
    const int m0 = blockIdx.x * 32;
    const int n0 = blockIdx.y * 64;

    const int lr = tid >> 2;            // 0..31
    const int kk = (tid & 3) * 4;       // 0,4,8,12

    float acc[4][4] = {};

    for (int k0 = 0; k0 < K; k0 += 16) {
        // Stage A tile (32x16) transposed into As[k][m]
        float4 a4 = *(const float4*)(A + (size_t)(m0 + lr) * K + k0 + kk);
        As[kk + 0][lr] = a4.x;
        As[kk + 1][lr] = a4.y;
        As[kk + 2][lr] = a4.z;
        As[kk + 3][lr] = a4.w;
        // Stage W tile (64x16) transposed into Ws[k][n]
        float4 w4 = *(const float4*)(W + (size_t)(n0 + lr) * K + k0 + kk);
        Ws[kk + 0][lr] = w4.x;
        Ws[kk + 1][lr] = w4.y;
        Ws[kk + 2][lr] = w4.z;
        Ws[kk + 3][lr] = w4.w;
        float4 w4b = *(const float4*)(W + (size_t)(n0 + lr + 32) * K + k0 + kk);
        Ws[kk + 0][lr + 32] = w4b.x;
        Ws[kk + 1][lr + 32] = w4b.y;
        Ws[kk + 2][lr + 32] = w4b.z;
        Ws[kk + 3][lr + 32] = w4b.w;
        __syncthreads();

        #pragma unroll
        for (int k = 0; k < 16; k++) {
            float4 av = *(const float4*)&As[k][ty * 4];
            float4 wv = *(const float4*)&Ws[k][tx * 4];
            float a[4] = {av.x, av.y, av.z, av.w};
            float w[4] = {wv.x, wv.y, wv.z, wv.w};
            #pragma unroll
            for (int i = 0; i < 4; i++)
                #pragma unroll
                for (int j = 0; j < 4; j++)
                    acc[i][j] = fmaf(a[i], w[j], acc[i][j]);
        }
        __syncthreads();
    }

    // Epilogue: vectorized float4 stores along n
    const int nbase = n0 + tx * 4;
    float4 bv = make_float4(0.f, 0.f, 0.f, 0.f);
    if (bias) bv = *(const float4*)(bias + nbase);
    #pragma unroll
    for (int i = 0; i < 4; i++) {
        int m = m0 + ty * 4 + i;
        float4 o;
        o.x = acc[i][0] + bv.x;
        o.y = acc[i][1] + bv.y;
        o.z = acc[i][2] + bv.z;
        o.w = acc[i][3] + bv.w;
        *(float4*)(C + (size_t)m * N + nbase) = o;
    }
}

// ---------------------------------------------------------------------------
// Fused score + tanh + softmax + context-vector kernel.
// Grid: (T/4, B). Block: 256 threads (8 warps). Each block handles 4 t-rows
// of one batch: align[b, t0..t0+3, :] and c[b, t0..t0+3, :].
// Writes align to output, writes [c | inp] into g_concat.
// ---------------------------------------------------------------------------
__global__ void attn_kernel(const float* __restrict__ wq,
                            const float* __restrict__ uh,
                            const float* __restrict__ v,
                            const float* __restrict__ context,
                            const float* __restrict__ inp,
                            float* __restrict__ align_out,
                            float* __restrict__ concat)
{
    __shared__ float v_sh[D_];
    __shared__ float wq_sh[4][D_];
    __shared__ float al_sh[4][S_];

    const int b = blockIdx.y;
    const int t0 = blockIdx.x * 4;
    const int tid = threadIdx.x;
    const int warp = tid >> 5;
    const int lane = tid & 31;

    for (int i = tid; i < D_; i += 256) {
        v_sh[i] = v[i];
        #pragma unroll
        for (int tt = 0; tt < 4; tt++)
            wq_sh[tt][i] = wq[((size_t)(b * T_ + t0 + tt)) * D_ + i];
    }
    __syncthreads();

    // ---- scores: align[tt][s] = sum_d v[d] * tanh(uh[b,s,d] + wq[tt][d]) ----
    for (int s = warp; s < S_; s += 8) {
        const float* urow = uh + ((size_t)(b * S_ + s)) * D_;
        float a0 = 0.f, a1 = 0.f, a2 = 0.f, a3 = 0.f;
        for (int d = lane; d < D_; d += 32) {
            float u = urow[d];
            float vd = v_sh[d];
            a0 = fmaf(vd, fast_tanh(u + wq_sh[0][d]), a0);
            a1 = fmaf(vd, fast_tanh(u + wq_sh[1][d]), a1);
            a2 = fmaf(vd, fast_tanh(u + wq_sh[2][d]), a2);
            a3 = fmaf(vd, fast_tanh(u + wq_sh[3][d]), a3);
        }
        #pragma unroll
        for (int o = 16; o; o >>= 1) {
            a0 += __shfl_xor_sync(0xFFFFFFFFu, a0, o);
            a1 += __shfl_xor_sync(0xFFFFFFFFu, a1, o);
            a2 += __shfl_xor_sync(0xFFFFFFFFu, a2, o);
            a3 += __shfl_xor_sync(0xFFFFFFFFu, a3, o);
        }
        if (lane == 0) {
            al_sh[0][s] = a0;
            al_sh[1][s] = a1;
            al_sh[2][s] = a2;
            al_sh[3][s] = a3;
        }
    }
    __syncthreads();

    // ---- softmax over s (warp tt handles t-row tt) ----
    if (warp < 4) {
        float m = -1e30f;
        for (int s = lane; s < S_; s += 32) m = fmaxf(m, al_sh[warp][s]);
        #pragma unroll
        for (int o = 16; o; o >>= 1)
            m = fmaxf(m, __shfl_xor_sync(0xFFFFFFFFu, m, o));
        float sum = 0.f;
        for (int s = lane; s < S_; s += 32) {
            float e = __expf(al_sh[warp][s] - m);
            al_sh[warp][s] = e;
            sum += e;
        }
        #pragma unroll
        for (int o = 16; o; o >>= 1)
            sum += __shfl_xor_sync(0xFFFFFFFFu, sum, o);
        float inv = 1.0f / sum;
        float* aout = align_out + ((size_t)(b * T_ + t0 + warp)) * S_;
        for (int s = lane; s < S_; s += 32) {
            float p = al_sh[warp][s] * inv;
            al_sh[warp][s] = p;
            aout[s] = p;
        }
    }
    __syncthreads();

    // ---- context vectors: c[tt][d] = sum_s p[tt][s] * context[b,s,d] ----
    const int d = tid * 2;   // each thread owns 2 adjacent d
    float c00 = 0.f, c01 = 0.f, c10 = 0.f, c11 = 0.f;
    float c20 = 0.f, c21 = 0.f, c30 = 0.f, c31 = 0.f;
    for (int s = 0; s < S_; s++) {
        float2 cx = *(const float2*)(context + ((size_t)(b * S_ + s)) * D_ + d);
        float p0 = al_sh[0][s], p1 = al_sh[1][s];
        float p2 = al_sh[2][s], p3 = al_sh[3][s];
        c00 = fmaf(p0, cx.x, c00); c01 = fmaf(p0, cx.y, c01);
        c10 = fmaf(p1, cx.x, c10); c11 = fmaf(p1, cx.y, c11);
        c20 = fmaf(p2, cx.x, c20); c21 = fmaf(p2, cx.y, c21);
        c30 = fmaf(p3, cx.x, c30); c31 = fmaf(p3, cx.y, c31);
    }
    float2 cs[4] = {make_float2(c00, c01), make_float2(c10, c11),
                    make_float2(c20, c21), make_float2(c30, c31)};
    #pragma unroll
    for (int tt = 0; tt < 4; tt++) {
        size_t row = (size_t)(b * T_ + t0 + tt);
        *(float2*)(concat + row * (2 * D_) + d) = cs[tt];
        float2 iv = *(const float2*)(inp + row * D_ + d);
        *(float2*)(concat + row * (2 * D_) + D_ + d) = iv;
    }
}

// ---------------------------------------------------------------------------
extern "C" void kernel_launch(void* const* d_in, const int* in_sizes, int n_in,
                              void* d_out, int out_size)
{
    const float* inp     = (const float*)d_in[0];
    const float* context = (const float*)d_in[1];
    const float* Wq      = (const float*)d_in[2];
    const float* bq      = (const float*)d_in[3];
    const float* Wc      = (const float*)d_in[4];
    const float* v       = (const float*)d_in[5];
    const float* Wout    = (const float*)d_in[6];
    const float* bout    = (const float*)d_in[7];

    float* out    = (float*)d_out;
    float* attn_h = out;                       // (B,T,D)
    float* align  = out + (size_t)B_ * T_ * D_;// (B,T,S)

    float *p_wq, *p_uh, *p_concat;
    cudaGetSymbolAddress((void**)&p_wq, g_wq);
    cudaGetSymbolAddress((void**)&p_uh, g_uh);
    cudaGetSymbolAddress((void**)&p_concat, g_concat);

    // wq = inp @ Wq^T + bq : M=B*T=512, N=512, K=512
    gemm_nt_kernel<<<dim3(512 / 32, 512 / 64), 128>>>(inp, Wq, bq, p_wq,
                                                      B_ * T_, D_, D_);
    // uh = context @ Wc^T : M=B*S=2048, N=512, K=512
    gemm_nt_kernel<<<dim3(2048 / 32, 512 / 64), 128>>>(context, Wc, nullptr, p_uh,
                                                       B_ * S_, D_, D_);
    // fused scores + softmax + context vectors
    attn_kernel<<<dim3(T_ / 4, B_), 256>>>(p_wq, p_uh, v, context, inp,
                                           align, p_concat);
    // attn_h = [c|inp] @ Wout^T + bout : M=512, N=512, K=1024
    gemm_nt_kernel<<<dim3(512 / 32, 512 / 64), 128>>>(p_concat, Wout, bout, attn_h,
                                                      B_ * T_, D_, 2 * D_);
}

// round 5
// speedup vs baseline: 1.0423x; 1.0423x over previous
#include <cuda_runtime.h>

#define B_ 4
#define T_ 128
#define S_ 512
#define D_ 512

// Scratch (allocation-free rule: __device__ globals)
__device__ __align__(16) float g_wq [B_ * T_ * D_];          // 1 MB
__device__ __align__(16) float g_uh [B_ * S_ * D_];          // 4 MB
__device__ __align__(16) float g_pre[B_ * T_ * D_];          // 1 MB  inp @ WoutR^T + bout
__device__ __align__(16) float g_c  [B_ * T_ * D_];          // 1 MB  context vectors
__device__ __align__(16) float g_p3 [4 * B_ * T_ * D_];      // 4 MB  split-K partials

__device__ __forceinline__ float fast_tanh(float x) {
    float y;
    asm("tanh.approx.f32 %0, %1;" : "=f"(y) : "f"(x));
    return y;
}

// ---------------------------------------------------------------------------
// Segmented NT GEMM: per m-block segment s:
//   C[m,n] = sum_k A[m,k]*W[n,k] (+bias[n]),  A row-major lda, W row-major ldw
// BM=BN=64, BK=16, 256 threads, 4x4 microtile, double-buffered smem.
// blockIdx.z = split-K index (kLen elements each), C offset by z*partStride.
// ---------------------------------------------------------------------------
struct GemmArgs {
    const float* A[3];
    const float* W[3];
    const float* bias[3];
    float*       C[3];
    int lda[3], ldw[3], ldc[3];
    int segEnd[3];      // cumulative m-block boundaries
    int kLen;           // K handled per z-split
    long partStride;    // C element offset per z
};

__global__ __launch_bounds__(256) void gemm_seg_kernel(GemmArgs args)
{
    __shared__ float As[2][16][68];
    __shared__ float Ws[2][16][68];

    const int bm = blockIdx.x;
    int seg = 0;
    if (bm >= args.segEnd[0]) seg = 1;
    if (bm >= args.segEnd[1]) seg = 2;
    const int segStart = (seg == 0) ? 0 : args.segEnd[seg - 1];

    const float* A    = args.A[seg];
    const float* W    = args.W[seg];
    const float* bias = args.bias[seg];
    float*       C    = args.C[seg] + (long)blockIdx.z * args.partStride;
    const int lda = args.lda[seg], ldw = args.ldw[seg], ldc = args.ldc[seg];

    const int m0 = (bm - segStart) * 64;
    const int n0 = blockIdx.y * 64;

    const int tid = threadIdx.x;
    const int tx = tid & 15;        // n
    const int ty = tid >> 4;        // m
    const int lr = tid >> 2;        // 0..63 staging row
    const int lc = (tid & 3) * 4;   // 0,4,8,12 staging k

    const int kStart = blockIdx.z * args.kLen;
    const float* Aptr = A + (long)(m0 + lr) * lda + kStart + lc;
    const float* Wptr = W + (long)(n0 + lr) * ldw + kStart + lc;
    const int nChunks = args.kLen / 16;

    float acc[4][4] = {};

    // stage chunk 0
    float4 pa = *(const float4*)Aptr;
    float4 pw = *(const float4*)Wptr;
    As[0][lc + 0][lr] = pa.x; As[0][lc + 1][lr] = pa.y;
    As[0][lc + 2][lr] = pa.z; As[0][lc + 3][lr] = pa.w;
    Ws[0][lc + 0][lr] = pw.x; Ws[0][lc + 1][lr] = pw.y;
    Ws[0][lc + 2][lr] = pw.z; Ws[0][lc + 3][lr] = pw.w;

    for (int c = 0; c < nChunks; c++) {
        __syncthreads();
        const int buf = c & 1;
        if (c + 1 < nChunks) {
            pa = *(const float4*)(Aptr + (c + 1) * 16);
            pw = *(const float4*)(Wptr + (c + 1) * 16);
        }
        #pragma unroll
        for (int k = 0; k < 16; k++) {
            float4 av = *(const float4*)&As[buf][k][ty * 4];
            float4 wv = *(const float4*)&Ws[buf][k][tx * 4];
            float a[4] = {av.x, av.y, av.z, av.w};
            float w[4] = {wv.x, wv.y, wv.z, wv.w};
            #pragma unroll
            for (int i = 0; i < 4; i++)
                #pragma unroll
                for (int j = 0; j < 4; j++)
                    acc[i][j] = fmaf(a[i], w[j], acc[i][j]);
        }
        if (c + 1 < nChunks) {
            const int nb = buf ^ 1;
            As[nb][lc + 0][lr] = pa.x; As[nb][lc + 1][lr] = pa.y;
            As[nb][lc + 2][lr] = pa.z; As[nb][lc + 3][lr] = pa.w;
            Ws[nb][lc + 0][lr] = pw.x; Ws[nb][lc + 1][lr] = pw.y;
            Ws[nb][lc + 2][lr] = pw.z; Ws[nb][lc + 3][lr] = pw.w;
        }
    }

    const int nbase = n0 + tx * 4;
    float4 bv = make_float4(0.f, 0.f, 0.f, 0.f);
    if (bias) bv = *(const float4*)(bias + nbase);
    #pragma unroll
    for (int i = 0; i < 4; i++) {
        const int m = m0 + ty * 4 + i;
        float4 o;
        o.x = acc[i][0] + bv.x;
        o.y = acc[i][1] + bv.y;
        o.z = acc[i][2] + bv.z;
        o.w = acc[i][3] + bv.w;
        *(float4*)(C + (long)m * ldc + nbase) = o;
    }
}

// ---------------------------------------------------------------------------
// Fused score + tanh + softmax + context-vector. TILE_T=2.
// Grid: (T/2, B), 256 threads (8 warps).
// ---------------------------------------------------------------------------
__global__ __launch_bounds__(256) void attn_kernel(
        const float* __restrict__ wq,
        const float* __restrict__ uh,
        const float* __restrict__ v,
        const float* __restrict__ context,
        float* __restrict__ align_out,
        float* __restrict__ c_out)
{
    __shared__ float v_sh[D_];
    __shared__ float wq_sh[2][D_];
    __shared__ float al_sh[2][S_];

    const int b = blockIdx.y;
    const int t0 = blockIdx.x * 2;
    const int tid = threadIdx.x;
    const int warp = tid >> 5;
    const int lane = tid & 31;

    for (int i = tid; i < D_; i += 256) {
        v_sh[i] = v[i];
        wq_sh[0][i] = wq[((long)(b * T_ + t0 + 0)) * D_ + i];
        wq_sh[1][i] = wq[((long)(b * T_ + t0 + 1)) * D_ + i];
    }
    __syncthreads();

    // scores
    for (int s = warp; s < S_; s += 8) {
        const float* urow = uh + ((long)(b * S_ + s)) * D_;
        float a0 = 0.f, a1 = 0.f;
        for (int d = lane; d < D_; d += 32) {
            float u = urow[d];
            float vd = v_sh[d];
            a0 = fmaf(vd, fast_tanh(u + wq_sh[0][d]), a0);
            a1 = fmaf(vd, fast_tanh(u + wq_sh[1][d]), a1);
        }
        #pragma unroll
        for (int o = 16; o; o >>= 1) {
            a0 += __shfl_xor_sync(0xFFFFFFFFu, a0, o);
            a1 += __shfl_xor_sync(0xFFFFFFFFu, a1, o);
        }
        if (lane == 0) { al_sh[0][s] = a0; al_sh[1][s] = a1; }
    }
    __syncthreads();

    // softmax over s: warp 0 -> t0, warp 1 -> t0+1
    if (warp < 2) {
        float m = -1e30f;
        for (int s = lane; s < S_; s += 32) m = fmaxf(m, al_sh[warp][s]);
        #pragma unroll
        for (int o = 16; o; o >>= 1)
            m = fmaxf(m, __shfl_xor_sync(0xFFFFFFFFu, m, o));
        float sum = 0.f;
        for (int s = lane; s < S_; s += 32) {
            float e = __expf(al_sh[warp][s] - m);
            al_sh[warp][s] = e;
            sum += e;
        }
        #pragma unroll
        for (int o = 16; o; o >>= 1)
            sum += __shfl_xor_sync(0xFFFFFFFFu, sum, o);
        float inv = 1.0f / sum;
        float* aout = align_out + ((long)(b * T_ + t0 + warp)) * S_;
        for (int s = lane; s < S_; s += 32) {
            float p = al_sh[warp][s] * inv;
            al_sh[warp][s] = p;
            aout[s] = p;
        }
    }
    __syncthreads();

    // context vectors: c[tt][d] = sum_s p[tt][s]*context[b,s,d]
    const int d = tid * 2;
    float c00 = 0.f, c01 = 0.f, c10 = 0.f, c11 = 0.f;
    for (int s = 0; s < S_; s++) {
        float2 cx = *(const float2*)(context + ((long)(b * S_ + s)) * D_ + d);
        float p0 = al_sh[0][s], p1 = al_sh[1][s];
        c00 = fmaf(p0, cx.x, c00); c01 = fmaf(p0, cx.y, c01);
        c10 = fmaf(p1, cx.x, c10); c11 = fmaf(p1, cx.y, c11);
    }
    *(float2*)(c_out + ((long)(b * T_ + t0 + 0)) * D_ + d) = make_float2(c00, c01);
    *(float2*)(c_out + ((long)(b * T_ + t0 + 1)) * D_ + d) = make_float2(c10, c11);
}

// ---------------------------------------------------------------------------
// attn_h = g_pre + sum_{z<4} g_p3[z]
// Total output: B*T*D = 262144 floats = 65536 float4 -> grid 256 x 256 thr.
// ---------------------------------------------------------------------------
__global__ __launch_bounds__(256) void reduce_kernel(
        const float4* __restrict__ pre,
        const float4* __restrict__ parts,
        float4* __restrict__ out)
{
    const int i = blockIdx.x * 256 + threadIdx.x;   // 0 .. 65535
    float4 r = pre[i];
    #pragma unroll
    for (int z = 0; z < 4; z++) {
        float4 p = parts[z * 65536 + i];
        r.x += p.x; r.y += p.y; r.z += p.z; r.w += p.w;
    }
    out[i] = r;
}

// ---------------------------------------------------------------------------
extern "C" void kernel_launch(void* const* d_in, const int* in_sizes, int n_in,
                              void* d_out, int out_size)
{
    const float* inp     = (const float*)d_in[0];
    const float* context = (const float*)d_in[1];
    const float* Wq      = (const float*)d_in[2];
    const float* bq      = (const float*)d_in[3];
    const float* Wc      = (const float*)d_in[4];
    const float* v       = (const float*)d_in[5];
    const float* Wout    = (const float*)d_in[6];
    const float* bout    = (const float*)d_in[7];

    float* out    = (float*)d_out;
    float* attn_h = out;                         // (B,T,D)
    float* align  = out + (long)B_ * T_ * D_;    // (B,T,S)

    float *p_wq, *p_uh, *p_pre, *p_c, *p_p3;
    cudaGetSymbolAddress((void**)&p_wq, g_wq);
    cudaGetSymbolAddress((void**)&p_uh, g_uh);
    cudaGetSymbolAddress((void**)&p_pre, g_pre);
    cudaGetSymbolAddress((void**)&p_c, g_c);
    cudaGetSymbolAddress((void**)&p_p3, g_p3);

    // ---- Launch 1: fused {wq, uh, pre} GEMMs, all K=512 ----
    GemmArgs a1;
    // seg0: wq = inp @ Wq^T + bq             (M=512)
    a1.A[0] = inp;     a1.W[0] = Wq;          a1.bias[0] = bq;   a1.C[0] = p_wq;
    a1.lda[0] = D_;    a1.ldw[0] = D_;        a1.ldc[0] = D_;
    // seg1: uh = context @ Wc^T              (M=2048)
    a1.A[1] = context; a1.W[1] = Wc;          a1.bias[1] = nullptr; a1.C[1] = p_uh;
    a1.lda[1] = D_;    a1.ldw[1] = D_;        a1.ldc[1] = D_;
    // seg2: pre = inp @ WoutR^T + bout       (M=512, WoutR = Wout[:,512:])
    a1.A[2] = inp;     a1.W[2] = Wout + D_;   a1.bias[2] = bout; a1.C[2] = p_pre;
    a1.lda[2] = D_;    a1.ldw[2] = 2 * D_;    a1.ldc[2] = D_;
    a1.segEnd[0] = 8; a1.segEnd[1] = 40; a1.segEnd[2] = 48;
    a1.kLen = D_;
    a1.partStride = 0;
    gemm_seg_kernel<<<dim3(48, 8, 1), 256>>>(a1);

    // ---- Launch 2: fused scores + softmax + context vectors ----
    attn_kernel<<<dim3(T_ / 2, B_), 256>>>(p_wq, p_uh, v, context, align, p_c);

    // ---- Launch 3: split-K=4 partials of c @ WoutL^T ----
    GemmArgs a3;
    a3.A[0] = p_c;  a3.W[0] = Wout;  a3.bias[0] = nullptr;  a3.C[0] = p_p3;
    a3.lda[0] = D_; a3.ldw[0] = 2 * D_; a3.ldc[0] = D_;
    a3.A[1] = a3.A[0]; a3.W[1] = a3.W[0]; a3.bias[1] = nullptr; a3.C[1] = a3.C[0];
    a3.lda[1] = a3.lda[0]; a3.ldw[1] = a3.ldw[0]; a3.ldc[1] = a3.ldc[0];
    a3.A[2] = a3.A[0]; a3.W[2] = a3.W[0]; a3.bias[2] = nullptr; a3.C[2] = a3.C[0];
    a3.lda[2] = a3.lda[0]; a3.ldw[2] = a3.ldw[0]; a3.ldc[2] = a3.ldc[0];
    a3.segEnd[0] = 8; a3.segEnd[1] = 8; a3.segEnd[2] = 8;
    a3.kLen = D_ / 4;                 // 128 per split
    a3.partStride = (long)B_ * T_ * D_;
    gemm_seg_kernel<<<dim3(8, 8, 4), 256>>>(a3);

    // ---- Launch 4: attn_h = pre + sum(parts) ----
    reduce_kernel<<<256, 256>>>((const float4*)p_pre, (const float4*)p_p3,
                                (float4*)attn_h);
}

// round 9
// speedup vs baseline: 1.5766x; 1.5125x over previous
#include <cuda_runtime.h>

#define B_ 4
#define T_ 128
#define S_ 512
#define D_ 512

// Scratch (allocation-free rule: __device__ globals)
__device__ __align__(16) float g_wq [B_ * T_ * D_];          // 1 MB
__device__ __align__(16) float g_uh [B_ * S_ * D_];          // 4 MB
__device__ __align__(16) float g_pre[B_ * T_ * D_];          // 1 MB  inp @ WoutR^T + bout
__device__ __align__(16) float g_c  [B_ * T_ * D_];          // 1 MB  context vectors
__device__ __align__(16) float g_p3 [4 * B_ * T_ * D_];      // 4 MB  split-K partials

__device__ __forceinline__ float fast_tanh(float x) {
    float y;
    asm("tanh.approx.f32 %0, %1;" : "=f"(y) : "f"(x));
    return y;
}

__device__ __forceinline__ unsigned to_tf32(float x) {
    unsigned u;
    asm("cvt.rna.tf32.f32 %0, %1;" : "=r"(u) : "f"(x));
    return u;
}

__device__ __forceinline__ void mma_tf32(float* d, const unsigned* a, const unsigned* b) {
    asm volatile(
        "mma.sync.aligned.m16n8k8.row.col.f32.tf32.tf32.f32 "
        "{%0,%1,%2,%3}, {%4,%5,%6,%7}, {%8,%9}, {%0,%1,%2,%3};"
        : "+f"(d[0]), "+f"(d[1]), "+f"(d[2]), "+f"(d[3])
        : "r"(a[0]), "r"(a[1]), "r"(a[2]), "r"(a[3]), "r"(b[0]), "r"(b[1]));
}

// ---------------------------------------------------------------------------
// Segmented NT GEMM on tensor cores (tf32 HMMA, fp32 accumulate).
//   C[m,n] = sum_k A[m,k]*W[n,k] (+bias[n])
// BM=BN=64, BK=16, 256 threads = 8 warps in 2(m) x 4(n); warp tile m32 x n16
// = 2x2 mma(m16n8k8) per k8-step. Double-buffered smem, padded strides
// (A: 20, W: 72) for conflict-free fragment loads.
// blockIdx.z = split-K index (kLen each), C offset by z*partStride.
// ---------------------------------------------------------------------------
struct GemmArgs {
    const float* A[3];
    const float* W[3];
    const float* bias[3];
    float*       C[3];
    int lda[3], ldw[3], ldc[3];
    int segEnd[3];      // cumulative m-block boundaries
    int kLen;           // K handled per z-split
    long partStride;    // C element offset per z
};

__global__ __launch_bounds__(256) void gemm_seg_kernel(GemmArgs args)
{
    __shared__ unsigned As[2][64][20];   // [m][k], tf32 bits, pad 16->20
    __shared__ unsigned Ws[2][16][72];   // [k][n], tf32 bits, pad 64->72

    const int bm = blockIdx.x;
    int seg = 0;
    if (bm >= args.segEnd[0]) seg = 1;
    if (bm >= args.segEnd[1]) seg = 2;
    const int segStart = (seg == 0) ? 0 : args.segEnd[seg - 1];

    const float* A    = args.A[seg];
    const float* W    = args.W[seg];
    const float* bias = args.bias[seg];
    float*       C    = args.C[seg] + (long)blockIdx.z * args.partStride;
    const int lda = args.lda[seg], ldw = args.ldw[seg], ldc = args.ldc[seg];

    const int m0 = (bm - segStart) * 64;
    const int n0 = blockIdx.y * 64;

    const int tid  = threadIdx.x;
    const int warp = tid >> 5;
    const int lane = tid & 31;
    const int wm   = warp >> 2;          // 0..1  (m32 tile)
    const int wn   = warp & 3;           // 0..3  (n16 tile)
    const int grp  = lane >> 2;          // 0..7
    const int qid  = lane & 3;           // 0..3

    const int lr = tid >> 2;             // 0..63 staging row
    const int lc = (tid & 3) * 4;        // 0,4,8,12 staging k

    const int kStart = blockIdx.z * args.kLen;
    const float* Aptr = A + (long)(m0 + lr) * lda + kStart + lc;
    const float* Wptr = W + (long)(n0 + lr) * ldw + kStart + lc;
    const int nChunks = args.kLen / 16;

    float acc[2][2][4] = {};             // [mi][nj][4]

    // stage chunk 0
    float4 pa = *(const float4*)Aptr;
    float4 pw = *(const float4*)Wptr;
    {
        uint4 ua = make_uint4(to_tf32(pa.x), to_tf32(pa.y), to_tf32(pa.z), to_tf32(pa.w));
        *(uint4*)&As[0][lr][lc] = ua;
        Ws[0][lc + 0][lr] = to_tf32(pw.x);
        Ws[0][lc + 1][lr] = to_tf32(pw.y);
        Ws[0][lc + 2][lr] = to_tf32(pw.z);
        Ws[0][lc + 3][lr] = to_tf32(pw.w);
    }

    for (int c = 0; c < nChunks; c++) {
        __syncthreads();
        const int buf = c & 1;
        if (c + 1 < nChunks) {
            pa = *(const float4*)(Aptr + (c + 1) * 16);
            pw = *(const float4*)(Wptr + (c + 1) * 16);
        }

        #pragma unroll
        for (int s = 0; s < 2; s++) {    // two k8 steps per chunk
            const int kk = s * 8 + qid;
            unsigned afr[2][4], bfr[2][2];
            #pragma unroll
            for (int i = 0; i < 2; i++) {
                const int mrow = wm * 32 + i * 16 + grp;
                afr[i][0] = As[buf][mrow    ][kk];
                afr[i][1] = As[buf][mrow + 8][kk];
                afr[i][2] = As[buf][mrow    ][kk + 4];
                afr[i][3] = As[buf][mrow + 8][kk + 4];
            }
            #pragma unroll
            for (int j = 0; j < 2; j++) {
                const int ncol = wn * 16 + j * 8 + grp;
                bfr[j][0] = Ws[buf][s * 8 + qid    ][ncol];
                bfr[j][1] = Ws[buf][s * 8 + qid + 4][ncol];
            }
            #pragma unroll
            for (int i = 0; i < 2; i++)
                #pragma unroll
                for (int j = 0; j < 2; j++)
                    mma_tf32(acc[i][j], afr[i], bfr[j]);
        }

        if (c + 1 < nChunks) {
            const int nb = buf ^ 1;
            uint4 ua = make_uint4(to_tf32(pa.x), to_tf32(pa.y), to_tf32(pa.z), to_tf32(pa.w));
            *(uint4*)&As[nb][lr][lc] = ua;
            Ws[nb][lc + 0][lr] = to_tf32(pw.x);
            Ws[nb][lc + 1][lr] = to_tf32(pw.y);
            Ws[nb][lc + 2][lr] = to_tf32(pw.z);
            Ws[nb][lc + 3][lr] = to_tf32(pw.w);
        }
    }

    // Epilogue: D fragment rows {grp, grp+8}, cols {2qid, 2qid+1}
    #pragma unroll
    for (int j = 0; j < 2; j++) {
        const int n = n0 + wn * 16 + j * 8 + 2 * qid;
        float b0 = 0.f, b1 = 0.f;
        if (bias) { b0 = bias[n]; b1 = bias[n + 1]; }
        #pragma unroll
        for (int i = 0; i < 2; i++) {
            const int m = m0 + wm * 32 + i * 16 + grp;
            *(float2*)(C + (long)m * ldc + n) =
                make_float2(acc[i][j][0] + b0, acc[i][j][1] + b1);
            *(float2*)(C + (long)(m + 8) * ldc + n) =
                make_float2(acc[i][j][2] + b0, acc[i][j][3] + b1);
        }
    }
}

// ---------------------------------------------------------------------------
// Fused score + tanh + softmax + context-vector. TILE_T=4.
// Grid: (T/4, B), 512 threads (16 warps).
// ---------------------------------------------------------------------------
__global__ __launch_bounds__(512) void attn_kernel(
        const float* __restrict__ wq,
        const float* __restrict__ uh,
        const float* __restrict__ v,
        const float* __restrict__ context,
        float* __restrict__ align_out,
        float* __restrict__ c_out)
{
    __shared__ float v_sh[D_];
    __shared__ float wq_sh[4][D_];
    __shared__ float al_sh[4][S_];

    const int b = blockIdx.y;
    const int t0 = blockIdx.x * 4;
    const int tid = threadIdx.x;
    const int warp = tid >> 5;
    const int lane = tid & 31;

    {
        const int i = tid;   // 512 threads cover D_=512 exactly
        v_sh[i] = v[i];
        #pragma unroll
        for (int tt = 0; tt < 4; tt++)
            wq_sh[tt][i] = wq[((long)(b * T_ + t0 + tt)) * D_ + i];
    }
    __syncthreads();

    // scores
    for (int s = warp; s < S_; s += 16) {
        const float* urow = uh + ((long)(b * S_ + s)) * D_;
        float a0 = 0.f, a1 = 0.f, a2 = 0.f, a3 = 0.f;
        for (int d = lane; d < D_; d += 32) {
            float u = urow[d];
            float vd = v_sh[d];
            a0 = fmaf(vd, fast_tanh(u + wq_sh[0][d]), a0);
            a1 = fmaf(vd, fast_tanh(u + wq_sh[1][d]), a1);
            a2 = fmaf(vd, fast_tanh(u + wq_sh[2][d]), a2);
            a3 = fmaf(vd, fast_tanh(u + wq_sh[3][d]), a3);
        }
        #pragma unroll
        for (int o = 16; o; o >>= 1) {
            a0 += __shfl_xor_sync(0xFFFFFFFFu, a0, o);
            a1 += __shfl_xor_sync(0xFFFFFFFFu, a1, o);
            a2 += __shfl_xor_sync(0xFFFFFFFFu, a2, o);
            a3 += __shfl_xor_sync(0xFFFFFFFFu, a3, o);
        }
        if (lane == 0) {
            al_sh[0][s] = a0; al_sh[1][s] = a1;
            al_sh[2][s] = a2; al_sh[3][s] = a3;
        }
    }
    __syncthreads();

    // softmax over s: warp tt handles row t0+tt
    if (warp < 4) {
        float m = -1e30f;
        for (int s = lane; s < S_; s += 32) m = fmaxf(m, al_sh[warp][s]);
        #pragma unroll
        for (int o = 16; o; o >>= 1)
            m = fmaxf(m, __shfl_xor_sync(0xFFFFFFFFu, m, o));
        float sum = 0.f;
        for (int s = lane; s < S_; s += 32) {
            float e = __expf(al_sh[warp][s] - m);
            al_sh[warp][s] = e;
            sum += e;
        }
        #pragma unroll
        for (int o = 16; o; o >>= 1)
            sum += __shfl_xor_sync(0xFFFFFFFFu, sum, o);
        float inv = 1.0f / sum;
        float* aout = align_out + ((long)(b * T_ + t0 + warp)) * S_;
        for (int s = lane; s < S_; s += 32) {
            float p = al_sh[warp][s] * inv;
            al_sh[warp][s] = p;
            aout[s] = p;
        }
    }
    __syncthreads();

    // context vectors: c[tt][d] = sum_s p[tt][s]*context[b,s,d]; d = tid
    const int d = tid;
    float c0 = 0.f, c1 = 0.f, c2 = 0.f, c3 = 0.f;
    const float* cptr = context + ((long)b * S_) * D_ + d;
    for (int s = 0; s < S_; s++) {
        float cx = cptr[(long)s * D_];
        c0 = fmaf(al_sh[0][s], cx, c0);
        c1 = fmaf(al_sh[1][s], cx, c1);
        c2 = fmaf(al_sh[2][s], cx, c2);
        c3 = fmaf(al_sh[3][s], cx, c3);
    }
    c_out[((long)(b * T_ + t0 + 0)) * D_ + d] = c0;
    c_out[((long)(b * T_ + t0 + 1)) * D_ + d] = c1;
    c_out[((long)(b * T_ + t0 + 2)) * D_ + d] = c2;
    c_out[((long)(b * T_ + t0 + 3)) * D_ + d] = c3;
}

// ---------------------------------------------------------------------------
// attn_h = g_pre + sum_{z<4} g_p3[z]
// Total output: B*T*D = 262144 floats = 65536 float4 -> grid 256 x 256 thr.
// ---------------------------------------------------------------------------
__global__ __launch_bounds__(256) void reduce_kernel(
        const float4* __restrict__ pre,
        const float4* __restrict__ parts,
        float4* __restrict__ out)
{
    const int i = blockIdx.x * 256 + threadIdx.x;   // 0 .. 65535
    float4 r = pre[i];
    #pragma unroll
    for (int z = 0; z < 4; z++) {
        float4 p = parts[z * 65536 + i];
        r.x += p.x; r.y += p.y; r.z += p.z; r.w += p.w;
    }
    out[i] = r;
}

// ---------------------------------------------------------------------------
extern "C" void kernel_launch(void* const* d_in, const int* in_sizes, int n_in,
                              void* d_out, int out_size)
{
    const float* inp     = (const float*)d_in[0];
    const float* context = (const float*)d_in[1];
    const float* Wq      = (const float*)d_in[2];
    const float* bq      = (const float*)d_in[3];
    const float* Wc      = (const float*)d_in[4];
    const float* v       = (const float*)d_in[5];
    const float* Wout    = (const float*)d_in[6];
    const float* bout    = (const float*)d_in[7];

    float* out    = (float*)d_out;
    float* attn_h = out;                         // (B,T,D)
    float* align  = out + (long)B_ * T_ * D_;    // (B,T,S)

    float *p_wq, *p_uh, *p_pre, *p_c, *p_p3;
    cudaGetSymbolAddress((void**)&p_wq, g_wq);
    cudaGetSymbolAddress((void**)&p_uh, g_uh);
    cudaGetSymbolAddress((void**)&p_pre, g_pre);
    cudaGetSymbolAddress((void**)&p_c, g_c);
    cudaGetSymbolAddress((void**)&p_p3, g_p3);

    // ---- Launch 1: fused {wq, uh, pre} GEMMs, all K=512 ----
    GemmArgs a1;
    // seg0: wq = inp @ Wq^T + bq             (M=512)
    a1.A[0] = inp;     a1.W[0] = Wq;          a1.bias[0] = bq;   a1.C[0] = p_wq;
    a1.lda[0] = D_;    a1.ldw[0] = D_;        a1.ldc[0] = D_;
    // seg1: uh = context @ Wc^T              (M=2048)
    a1.A[1] = context; a1.W[1] = Wc;          a1.bias[1] = nullptr; a1.C[1] = p_uh;
    a1.lda[1] = D_;    a1.ldw[1] = D_;        a1.ldc[1] = D_;
    // seg2: pre = inp @ WoutR^T + bout       (M=512, WoutR = Wout[:,512:])
    a1.A[2] = inp;     a1.W[2] = Wout + D_;   a1.bias[2] = bout; a1.C[2] = p_pre;
    a1.lda[2] = D_;    a1.ldw[2] = 2 * D_;    a1.ldc[2] = D_;
    a1.segEnd[0] = 8; a1.segEnd[1] = 40; a1.segEnd[2] = 48;
    a1.kLen = D_;
    a1.partStride = 0;
    gemm_seg_kernel<<<dim3(48, 8, 1), 256>>>(a1);

    // ---- Launch 2: fused scores + softmax + context vectors ----
    attn_kernel<<<dim3(T_ / 4, B_), 512>>>(p_wq, p_uh, v, context, align, p_c);

    // ---- Launch 3: split-K=4 partials of c @ WoutL^T ----
    GemmArgs a3;
    a3.A[0] = p_c;  a3.W[0] = Wout;  a3.bias[0] = nullptr;  a3.C[0] = p_p3;
    a3.lda[0] = D_; a3.ldw[0] = 2 * D_; a3.ldc[0] = D_;
    a3.A[1] = a3.A[0]; a3.W[1] = a3.W[0]; a3.bias[1] = nullptr; a3.C[1] = a3.C[0];
    a3.lda[1] = a3.lda[0]; a3.ldw[1] = a3.ldw[0]; a3.ldc[1] = a3.ldc[0];
    a3.A[2] = a3.A[0]; a3.W[2] = a3.W[0]; a3.bias[2] = nullptr; a3.C[2] = a3.C[0];
    a3.lda[2] = a3.lda[0]; a3.ldw[2] = a3.ldw[0]; a3.ldc[2] = a3.ldc[0];
    a3.segEnd[0] = 8; a3.segEnd[1] = 8; a3.segEnd[2] = 8;
    a3.kLen = D_ / 4;                 // 128 per split
    a3.partStride = (long)B_ * T_ * D_;
    gemm_seg_kernel<<<dim3(8, 8, 4), 256>>>(a3);

    // ---- Launch 4: attn_h = pre + sum(parts) ----
    reduce_kernel<<<256, 256>>>((const float4*)p_pre, (const float4*)p_p3,
                                (float4*)attn_h);
}

// round 11
// speedup vs baseline: 1.9807x; 1.2564x over previous
#include <cuda_runtime.h>

#define B_ 4
#define T_ 128
#define S_ 512
#define D_ 512

// Scratch (allocation-free rule: __device__ globals)
__device__ __align__(16) float g_wq [B_ * T_ * D_];          // 1 MB
__device__ __align__(16) float g_uh [B_ * S_ * D_];          // 4 MB
__device__ __align__(16) float g_pre[B_ * T_ * D_];          // 1 MB  inp @ WoutR^T + bout
__device__ __align__(16) float g_c  [B_ * T_ * D_];          // 1 MB  context vectors

__device__ __forceinline__ float fast_tanh(float x) {
    float y;
    asm("tanh.approx.f32 %0, %1;" : "=f"(y) : "f"(x));
    return y;
}

__device__ __forceinline__ unsigned to_tf32(float x) {
    unsigned u;
    asm("cvt.rna.tf32.f32 %0, %1;" : "=r"(u) : "f"(x));
    return u;
}

__device__ __forceinline__ void mma_tf32(float* d, const unsigned* a, const unsigned* b) {
    asm volatile(
        "mma.sync.aligned.m16n8k8.row.col.f32.tf32.tf32.f32 "
        "{%0,%1,%2,%3}, {%4,%5,%6,%7}, {%8,%9}, {%0,%1,%2,%3};"
        : "+f"(d[0]), "+f"(d[1]), "+f"(d[2]), "+f"(d[3])
        : "r"(a[0]), "r"(a[1]), "r"(a[2]), "r"(a[3]), "r"(b[0]), "r"(b[1]));
}

// ---------------------------------------------------------------------------
// Segmented NT GEMM on tensor cores (tf32 HMMA, fp32 accumulate).
//   C[m,n] = sum_k A[m,k]*W[n,k] (+bias[n]) (+addC[m,n])
// BM=BN=64, BK=16, 256 threads = 8 warps (2m x 4n); warp tile m32 x n16.
// Both A and W staged in [row][k] layout, pad 16->20 words: staging stores
// and fragment loads are bank-conflict-free.
// ---------------------------------------------------------------------------
struct GemmArgs {
    const float* A[3];
    const float* W[3];
    const float* bias[3];
    const float* addC[3];     // optional per-(m,n) addend (uses ldc)
    float*       C[3];
    int lda[3], ldw[3], ldc[3];
    int segEnd[3];            // cumulative m-block boundaries
};

__global__ __launch_bounds__(256) void gemm_seg_kernel(GemmArgs args, int K)
{
    __shared__ unsigned As[2][64][20];   // [m][k] tf32 bits
    __shared__ unsigned Ws[2][64][20];   // [n][k] tf32 bits

    const int bm = blockIdx.x;
    int seg = 0;
    if (bm >= args.segEnd[0]) seg = 1;
    if (bm >= args.segEnd[1]) seg = 2;
    const int segStart = (seg == 0) ? 0 : args.segEnd[seg - 1];

    const float* A    = args.A[seg];
    const float* W    = args.W[seg];
    const float* bias = args.bias[seg];
    const float* addC = args.addC[seg];
    float*       C    = args.C[seg];
    const int lda = args.lda[seg], ldw = args.ldw[seg], ldc = args.ldc[seg];

    const int m0 = (bm - segStart) * 64;
    const int n0 = blockIdx.y * 64;

    const int tid  = threadIdx.x;
    const int warp = tid >> 5;
    const int lane = tid & 31;
    const int wm   = warp >> 2;          // 0..1  (m32 tile)
    const int wn   = warp & 3;           // 0..3  (n16 tile)
    const int grp  = lane >> 2;          // 0..7
    const int qid  = lane & 3;           // 0..3

    const int lr = tid >> 2;             // 0..63 staging row
    const int lc = (tid & 3) * 4;        // 0,4,8,12 staging k

    const float* Aptr = A + (long)(m0 + lr) * lda + lc;
    const float* Wptr = W + (long)(n0 + lr) * ldw + lc;
    const int nChunks = K / 16;

    float acc[2][2][4] = {};             // [mi][nj][4]

    // stage chunk 0
    float4 pa = *(const float4*)Aptr;
    float4 pw = *(const float4*)Wptr;
    {
        uint4 ua = make_uint4(to_tf32(pa.x), to_tf32(pa.y), to_tf32(pa.z), to_tf32(pa.w));
        uint4 uw = make_uint4(to_tf32(pw.x), to_tf32(pw.y), to_tf32(pw.z), to_tf32(pw.w));
        *(uint4*)&As[0][lr][lc] = ua;
        *(uint4*)&Ws[0][lr][lc] = uw;
    }

    for (int c = 0; c < nChunks; c++) {
        __syncthreads();
        const int buf = c & 1;
        if (c + 1 < nChunks) {
            pa = *(const float4*)(Aptr + (c + 1) * 16);
            pw = *(const float4*)(Wptr + (c + 1) * 16);
        }

        #pragma unroll
        for (int s = 0; s < 2; s++) {    // two k8 steps per chunk
            const int kk = s * 8 + qid;
            unsigned afr[2][4], bfr[2][2];
            #pragma unroll
            for (int i = 0; i < 2; i++) {
                const int mrow = wm * 32 + i * 16 + grp;
                afr[i][0] = As[buf][mrow    ][kk];
                afr[i][1] = As[buf][mrow + 8][kk];
                afr[i][2] = As[buf][mrow    ][kk + 4];
                afr[i][3] = As[buf][mrow + 8][kk + 4];
            }
            #pragma unroll
            for (int j = 0; j < 2; j++) {
                const int ncol = wn * 16 + j * 8 + grp;
                bfr[j][0] = Ws[buf][ncol][kk];
                bfr[j][1] = Ws[buf][ncol][kk + 4];
            }
            #pragma unroll
            for (int i = 0; i < 2; i++)
                #pragma unroll
                for (int j = 0; j < 2; j++)
                    mma_tf32(acc[i][j], afr[i], bfr[j]);
        }

        if (c + 1 < nChunks) {
            const int nb = buf ^ 1;
            uint4 ua = make_uint4(to_tf32(pa.x), to_tf32(pa.y), to_tf32(pa.z), to_tf32(pa.w));
            uint4 uw = make_uint4(to_tf32(pw.x), to_tf32(pw.y), to_tf32(pw.z), to_tf32(pw.w));
            *(uint4*)&As[nb][lr][lc] = ua;
            *(uint4*)&Ws[nb][lr][lc] = uw;
        }
    }

    // Epilogue: D fragment rows {grp, grp+8}, cols {2qid, 2qid+1}
    #pragma unroll
    for (int j = 0; j < 2; j++) {
        const int n = n0 + wn * 16 + j * 8 + 2 * qid;
        float b0 = 0.f, b1 = 0.f;
        if (bias) { b0 = bias[n]; b1 = bias[n + 1]; }
        #pragma unroll
        for (int i = 0; i < 2; i++) {
            const int m = m0 + wm * 32 + i * 16 + grp;
            float2 r0 = make_float2(acc[i][j][0] + b0, acc[i][j][1] + b1);
            float2 r1 = make_float2(acc[i][j][2] + b0, acc[i][j][3] + b1);
            if (addC) {
                float2 p0 = *(const float2*)(addC + (long)m * ldc + n);
                float2 p1 = *(const float2*)(addC + (long)(m + 8) * ldc + n);
                r0.x += p0.x; r0.y += p0.y;
                r1.x += p1.x; r1.y += p1.y;
            }
            *(float2*)(C + (long)m * ldc + n)       = r0;
            *(float2*)(C + (long)(m + 8) * ldc + n) = r1;
        }
    }
}

// ---------------------------------------------------------------------------
// Fused score + tanh + softmax + context-vector. TILE_T=4.
// Grid: (T/4, B), 512 threads (16 warps). Each warp handles s-PAIRS
// (s, s+1), vectorized float4 loads, 8 independent accumulator chains.
// ---------------------------------------------------------------------------
__global__ __launch_bounds__(512) void attn_kernel(
        const float* __restrict__ wq,
        const float* __restrict__ uh,
        const float* __restrict__ v,
        const float* __restrict__ context,
        float* __restrict__ align_out,
        float* __restrict__ c_out)
{
    __shared__ float v_sh[D_];
    __shared__ float wq_sh[4][D_];
    __shared__ float al_sh[4][S_];

    const int b = blockIdx.y;
    const int t0 = blockIdx.x * 4;
    const int tid = threadIdx.x;
    const int warp = tid >> 5;
    const int lane = tid & 31;

    {
        v_sh[tid] = v[tid];
        #pragma unroll
        for (int tt = 0; tt < 4; tt++)
            wq_sh[tt][tid] = wq[((long)(b * T_ + t0 + tt)) * D_ + tid];
    }
    __syncthreads();

    // ---- scores: warp handles s-pairs {2w, 2w+1} stepping by 32 ----
    for (int s = warp * 2; s < S_; s += 32) {
        const float4* u0 = (const float4*)(uh + ((long)(b * S_ + s)) * D_);
        const float4* u1 = u0 + (D_ / 4);
        float acc[2][4] = {};
        #pragma unroll
        for (int i = 0; i < 4; i++) {
            const int idx = lane + 32 * i;
            float4 x0 = u0[idx];
            float4 x1 = u1[idx];
            float4 vf = ((const float4*)v_sh)[idx];
            float4 q0 = ((const float4*)wq_sh[0])[idx];
            float4 q1 = ((const float4*)wq_sh[1])[idx];
            float4 q2 = ((const float4*)wq_sh[2])[idx];
            float4 q3 = ((const float4*)wq_sh[3])[idx];
            float u0a[4] = {x0.x, x0.y, x0.z, x0.w};
            float u1a[4] = {x1.x, x1.y, x1.z, x1.w};
            float va[4]  = {vf.x, vf.y, vf.z, vf.w};
            float qa[4][4] = {{q0.x, q0.y, q0.z, q0.w},
                              {q1.x, q1.y, q1.z, q1.w},
                              {q2.x, q2.y, q2.z, q2.w},
                              {q3.x, q3.y, q3.z, q3.w}};
            #pragma unroll
            for (int cidx = 0; cidx < 4; cidx++) {
                const float vd = va[cidx];
                #pragma unroll
                for (int tt = 0; tt < 4; tt++) {
                    acc[0][tt] = fmaf(vd, fast_tanh(u0a[cidx] + qa[tt][cidx]), acc[0][tt]);
                    acc[1][tt] = fmaf(vd, fast_tanh(u1a[cidx] + qa[tt][cidx]), acc[1][tt]);
                }
            }
        }
        #pragma unroll
        for (int o = 16; o; o >>= 1) {
            #pragma unroll
            for (int p = 0; p < 2; p++)
                #pragma unroll
                for (int tt = 0; tt < 4; tt++)
                    acc[p][tt] += __shfl_xor_sync(0xFFFFFFFFu, acc[p][tt], o);
        }
        if (lane == 0) {
            #pragma unroll
            for (int tt = 0; tt < 4; tt++) {
                al_sh[tt][s]     = acc[0][tt];
                al_sh[tt][s + 1] = acc[1][tt];
            }
        }
    }
    __syncthreads();

    // ---- softmax over s: warp tt handles row t0+tt ----
    if (warp < 4) {
        float m = -1e30f;
        for (int s = lane; s < S_; s += 32) m = fmaxf(m, al_sh[warp][s]);
        #pragma unroll
        for (int o = 16; o; o >>= 1)
            m = fmaxf(m, __shfl_xor_sync(0xFFFFFFFFu, m, o));
        float sum = 0.f;
        for (int s = lane; s < S_; s += 32) {
            float e = __expf(al_sh[warp][s] - m);
            al_sh[warp][s] = e;
            sum += e;
        }
        #pragma unroll
        for (int o = 16; o; o >>= 1)
            sum += __shfl_xor_sync(0xFFFFFFFFu, sum, o);
        float inv = 1.0f / sum;
        float* aout = align_out + ((long)(b * T_ + t0 + warp)) * S_;
        for (int s = lane; s < S_; s += 32) {
            float p = al_sh[warp][s] * inv;
            al_sh[warp][s] = p;
            aout[s] = p;
        }
    }
    __syncthreads();

    // ---- context vectors: c[tt][d] = sum_s p[tt][s]*context[b,s,d]; d=tid ----
    const int d = tid;
    float c0 = 0.f, c1 = 0.f, c2 = 0.f, c3 = 0.f;
    const float* cptr = context + ((long)b * S_) * D_ + d;
    #pragma unroll 4
    for (int s = 0; s < S_; s++) {
        float cx = cptr[(long)s * D_];
        c0 = fmaf(al_sh[0][s], cx, c0);
        c1 = fmaf(al_sh[1][s], cx, c1);
        c2 = fmaf(al_sh[2][s], cx, c2);
        c3 = fmaf(al_sh[3][s], cx, c3);
    }
    c_out[((long)(b * T_ + t0 + 0)) * D_ + d] = c0;
    c_out[((long)(b * T_ + t0 + 1)) * D_ + d] = c1;
    c_out[((long)(b * T_ + t0 + 2)) * D_ + d] = c2;
    c_out[((long)(b * T_ + t0 + 3)) * D_ + d] = c3;
}

// ---------------------------------------------------------------------------
extern "C" void kernel_launch(void* const* d_in, const int* in_sizes, int n_in,
                              void* d_out, int out_size)
{
    const float* inp     = (const float*)d_in[0];
    const float* context = (const float*)d_in[1];
    const float* Wq      = (const float*)d_in[2];
    const float* bq      = (const float*)d_in[3];
    const float* Wc      = (const float*)d_in[4];
    const float* v       = (const float*)d_in[5];
    const float* Wout    = (const float*)d_in[6];
    const float* bout    = (const float*)d_in[7];

    float* out    = (float*)d_out;
    float* attn_h = out;                         // (B,T,D)
    float* align  = out + (long)B_ * T_ * D_;    // (B,T,S)

    float *p_wq, *p_uh, *p_pre, *p_c;
    cudaGetSymbolAddress((void**)&p_wq, g_wq);
    cudaGetSymbolAddress((void**)&p_uh, g_uh);
    cudaGetSymbolAddress((void**)&p_pre, g_pre);
    cudaGetSymbolAddress((void**)&p_c, g_c);

    // ---- Launch 1: fused {wq, uh, pre} GEMMs, all K=512 ----
    GemmArgs a1;
    // seg0: wq = inp @ Wq^T + bq             (M=512)
    a1.A[0] = inp;     a1.W[0] = Wq;          a1.bias[0] = bq;      a1.addC[0] = nullptr;
    a1.C[0] = p_wq;    a1.lda[0] = D_;        a1.ldw[0] = D_;       a1.ldc[0] = D_;
    // seg1: uh = context @ Wc^T              (M=2048)
    a1.A[1] = context; a1.W[1] = Wc;          a1.bias[1] = nullptr; a1.addC[1] = nullptr;
    a1.C[1] = p_uh;    a1.lda[1] = D_;        a1.ldw[1] = D_;       a1.ldc[1] = D_;
    // seg2: pre = inp @ WoutR^T + bout       (M=512, WoutR = Wout[:,512:])
    a1.A[2] = inp;     a1.W[2] = Wout + D_;   a1.bias[2] = bout;    a1.addC[2] = nullptr;
    a1.C[2] = p_pre;   a1.lda[2] = D_;        a1.ldw[2] = 2 * D_;   a1.ldc[2] = D_;
    a1.segEnd[0] = 8; a1.segEnd[1] = 40; a1.segEnd[2] = 48;
    gemm_seg_kernel<<<dim3(48, 8, 1), 256>>>(a1, D_);

    // ---- Launch 2: fused scores + softmax + context vectors ----
    attn_kernel<<<dim3(T_ / 4, B_), 512>>>(p_wq, p_uh, v, context, align, p_c);

    // ---- Launch 3: attn_h = c @ WoutL^T + pre  (full K, epilogue fold) ----
    GemmArgs a3;
    a3.A[0] = p_c;  a3.W[0] = Wout;  a3.bias[0] = nullptr;  a3.addC[0] = p_pre;
    a3.C[0] = attn_h;
    a3.lda[0] = D_; a3.ldw[0] = 2 * D_; a3.ldc[0] = D_;
    a3.A[1] = a3.A[0]; a3.W[1] = a3.W[0]; a3.bias[1] = nullptr; a3.addC[1] = nullptr;
    a3.C[1] = a3.C[0]; a3.lda[1] = a3.lda[0]; a3.ldw[1] = a3.ldw[0]; a3.ldc[1] = a3.ldc[0];
    a3.A[2] = a3.A[0]; a3.W[2] = a3.W[0]; a3.bias[2] = nullptr; a3.addC[2] = nullptr;
    a3.C[2] = a3.C[0]; a3.lda[2] = a3.lda[0]; a3.ldw[2] = a3.ldw[0]; a3.ldc[2] = a3.ldc[0];
    a3.segEnd[0] = 8; a3.segEnd[1] = 8; a3.segEnd[2] = 8;
    gemm_seg_kernel<<<dim3(8, 8, 1), 256>>>(a3, D_);
}

// round 13
// speedup vs baseline: 2.0144x; 1.0170x over previous
#include <cuda_runtime.h>

#define B_ 4
#define T_ 128
#define S_ 512
#define D_ 512

// Scratch (allocation-free rule: __device__ globals)
__device__ __align__(16) float g_wq [B_ * T_ * D_];          // 1 MB
__device__ __align__(16) float g_uh [B_ * S_ * D_];          // 4 MB
__device__ __align__(16) float g_pre[B_ * T_ * D_];          // 1 MB  inp @ WoutR^T + bout
__device__ __align__(16) float g_c  [B_ * T_ * D_];          // 1 MB  context vectors

__device__ __forceinline__ float fast_tanh(float x) {
    float y;
    asm("tanh.approx.f32 %0, %1;" : "=f"(y) : "f"(x));
    return y;
}

__device__ __forceinline__ unsigned to_tf32(float x) {
    unsigned u;
    asm("cvt.rna.tf32.f32 %0, %1;" : "=r"(u) : "f"(x));
    return u;
}

__device__ __forceinline__ void mma_tf32(float* d, const unsigned* a, const unsigned* b) {
    asm volatile(
        "mma.sync.aligned.m16n8k8.row.col.f32.tf32.tf32.f32 "
        "{%0,%1,%2,%3}, {%4,%5,%6,%7}, {%8,%9}, {%0,%1,%2,%3};"
        : "+f"(d[0]), "+f"(d[1]), "+f"(d[2]), "+f"(d[3])
        : "r"(a[0]), "r"(a[1]), "r"(a[2]), "r"(a[3]), "r"(b[0]), "r"(b[1]));
}

__device__ __forceinline__ void ldsm_x4(unsigned& r0, unsigned& r1,
                                        unsigned& r2, unsigned& r3,
                                        unsigned addr) {
    asm volatile(
        "ldmatrix.sync.aligned.m8n8.x4.shared.b16 {%0,%1,%2,%3}, [%4];"
        : "=r"(r0), "=r"(r1), "=r"(r2), "=r"(r3) : "r"(addr));
}

// ---------------------------------------------------------------------------
// Segmented NT GEMM on tensor cores (tf32 HMMA, fp32 accumulate).
//   C[m,n] = sum_k A[m,k]*W[n,k] (+bias[n]) (+addC[m,n])
// BM=BN=64, BK=16, 256 threads = 8 warps (2m x 4n); warp tile m32 x n16.
// A and W staged in [row][k] layout (pad 16->20 words). Fragments loaded
// via ldmatrix.x4 (3 LDSM per k8-step instead of 12 scalar LDS).
// ---------------------------------------------------------------------------
struct GemmArgs {
    const float* A[3];
    const float* W[3];
    const float* bias[3];
    const float* addC[3];     // optional per-(m,n) addend (uses ldc)
    float*       C[3];
    int lda[3], ldw[3], ldc[3];
    int segEnd[3];            // cumulative m-block boundaries
};

__global__ __launch_bounds__(256) void gemm_seg_kernel(GemmArgs args, int K)
{
    __shared__ unsigned As[2][64][20];   // [m][k] tf32 bits
    __shared__ unsigned Ws[2][64][20];   // [n][k] tf32 bits

    const int bm = blockIdx.x;
    int seg = 0;
    if (bm >= args.segEnd[0]) seg = 1;
    if (bm >= args.segEnd[1]) seg = 2;
    const int segStart = (seg == 0) ? 0 : args.segEnd[seg - 1];

    const float* A    = args.A[seg];
    const float* W    = args.W[seg];
    const float* bias = args.bias[seg];
    const float* addC = args.addC[seg];
    float*       C    = args.C[seg];
    const int lda = args.lda[seg], ldw = args.ldw[seg], ldc = args.ldc[seg];

    const int m0 = (bm - segStart) * 64;
    const int n0 = blockIdx.y * 64;

    const int tid  = threadIdx.x;
    const int warp = tid >> 5;
    const int lane = tid & 31;
    const int wm   = warp >> 2;          // 0..1  (m32 tile)
    const int wn   = warp & 3;           // 0..3  (n16 tile)
    const int grp  = lane >> 2;          // 0..7
    const int qid  = lane & 3;           // 0..3

    const int lr = tid >> 2;             // 0..63 staging row
    const int lc = (tid & 3) * 4;        // 0,4,8,12 staging k

    // ldmatrix per-lane base addresses (byte offsets inside buffer 0)
    const int q  = lane >> 3;            // quadrant 0..3
    const int qr = lane & 7;             // row within quadrant
    unsigned baseAs, baseWs;
    {
        unsigned a64 = (unsigned)__cvta_generic_to_shared(&As[0][0][0]);
        unsigned w64 = (unsigned)__cvta_generic_to_shared(&Ws[0][0][0]);
        // A quadrants: rows {+0,+8,+0,+8}, cols {0,0,4,4}
        const int arow = wm * 32 + (q & 1) * 8 + qr;
        const int acol = (q >> 1) * 4;
        baseAs = a64 + (unsigned)((arow * 20 + acol) * 4);
        // B quadrants: rows {+0,+0,+8,+8}, cols {0,4,0,4}
        const int brow = wn * 16 + (q >> 1) * 8 + qr;
        const int bcol = (q & 1) * 4;
        baseWs = w64 + (unsigned)((brow * 20 + bcol) * 4);
    }
    const unsigned BUFB = 64u * 20u * 4u;   // 5120 bytes per buffer

    const float* Aptr = A + (long)(m0 + lr) * lda + lc;
    const float* Wptr = W + (long)(n0 + lr) * ldw + lc;
    const int nChunks = K / 16;

    float acc[2][2][4] = {};             // [mi][nj][4]

    // stage chunk 0
    float4 pa = *(const float4*)Aptr;
    float4 pw = *(const float4*)Wptr;
    {
        uint4 ua = make_uint4(to_tf32(pa.x), to_tf32(pa.y), to_tf32(pa.z), to_tf32(pa.w));
        uint4 uw = make_uint4(to_tf32(pw.x), to_tf32(pw.y), to_tf32(pw.z), to_tf32(pw.w));
        *(uint4*)&As[0][lr][lc] = ua;
        *(uint4*)&Ws[0][lr][lc] = uw;
    }

    for (int c = 0; c < nChunks; c++) {
        __syncthreads();
        const int buf = c & 1;
        const unsigned boff = buf ? BUFB : 0u;
        if (c + 1 < nChunks) {
            pa = *(const float4*)(Aptr + (c + 1) * 16);
            pw = *(const float4*)(Wptr + (c + 1) * 16);
        }

        #pragma unroll
        for (int s = 0; s < 2; s++) {    // two k8 steps per chunk
            const unsigned soff = boff + (unsigned)(s * 32);
            unsigned afr[2][4], bfr[4];
            ldsm_x4(afr[0][0], afr[0][1], afr[0][2], afr[0][3], baseAs + soff);
            ldsm_x4(afr[1][0], afr[1][1], afr[1][2], afr[1][3],
                    baseAs + soff + 16u * 20u * 4u);
            ldsm_x4(bfr[0], bfr[1], bfr[2], bfr[3], baseWs + soff);
            #pragma unroll
            for (int i = 0; i < 2; i++) {
                mma_tf32(acc[i][0], afr[i], &bfr[0]);
                mma_tf32(acc[i][1], afr[i], &bfr[2]);
            }
        }

        if (c + 1 < nChunks) {
            const int nb = buf ^ 1;
            uint4 ua = make_uint4(to_tf32(pa.x), to_tf32(pa.y), to_tf32(pa.z), to_tf32(pa.w));
            uint4 uw = make_uint4(to_tf32(pw.x), to_tf32(pw.y), to_tf32(pw.z), to_tf32(pw.w));
            *(uint4*)&As[nb][lr][lc] = ua;
            *(uint4*)&Ws[nb][lr][lc] = uw;
        }
    }

    // Epilogue: D fragment rows {grp, grp+8}, cols {2qid, 2qid+1}
    #pragma unroll
    for (int j = 0; j < 2; j++) {
        const int n = n0 + wn * 16 + j * 8 + 2 * qid;
        float b0 = 0.f, b1 = 0.f;
        if (bias) { b0 = bias[n]; b1 = bias[n + 1]; }
        #pragma unroll
        for (int i = 0; i < 2; i++) {
            const int m = m0 + wm * 32 + i * 16 + grp;
            float2 r0 = make_float2(acc[i][j][0] + b0, acc[i][j][1] + b1);
            float2 r1 = make_float2(acc[i][j][2] + b0, acc[i][j][3] + b1);
            if (addC) {
                float2 p0 = *(const float2*)(addC + (long)m * ldc + n);
                float2 p1 = *(const float2*)(addC + (long)(m + 8) * ldc + n);
                r0.x += p0.x; r0.y += p0.y;
                r1.x += p1.x; r1.y += p1.y;
            }
            *(float2*)(C + (long)m * ldc + n)       = r0;
            *(float2*)(C + (long)(m + 8) * ldc + n) = r1;
        }
    }
}

// ---------------------------------------------------------------------------
// Fused score + tanh + softmax + context-vector. TILE_T=4.
// Grid: (T/4, B), 512 threads (16 warps). Each warp handles s-PAIRS
// (s, s+1), vectorized float4 loads, 8 independent accumulator chains.
// ---------------------------------------------------------------------------
__global__ __launch_bounds__(512) void attn_kernel(
        const float* __restrict__ wq,
        const float* __restrict__ uh,
        const float* __restrict__ v,
        const float* __restrict__ context,
        float* __restrict__ align_out,
        float* __restrict__ c_out)
{
    __shared__ float v_sh[D_];
    __shared__ float wq_sh[4][D_];
    __shared__ float al_sh[4][S_];

    const int b = blockIdx.y;
    const int t0 = blockIdx.x * 4;
    const int tid = threadIdx.x;
    const int warp = tid >> 5;
    const int lane = tid & 31;

    {
        v_sh[tid] = v[tid];
        #pragma unroll
        for (int tt = 0; tt < 4; tt++)
            wq_sh[tt][tid] = wq[((long)(b * T_ + t0 + tt)) * D_ + tid];
    }
    __syncthreads();

    // ---- scores: warp handles s-pairs {2w, 2w+1} stepping by 32 ----
    for (int s = warp * 2; s < S_; s += 32) {
        const float4* u0 = (const float4*)(uh + ((long)(b * S_ + s)) * D_);
        const float4* u1 = u0 + (D_ / 4);
        float acc[2][4] = {};
        #pragma unroll
        for (int i = 0; i < 4; i++) {
            const int idx = lane + 32 * i;
            float4 x0 = u0[idx];
            float4 x1 = u1[idx];
            float4 vf = ((const float4*)v_sh)[idx];
            float4 q0 = ((const float4*)wq_sh[0])[idx];
            float4 q1 = ((const float4*)wq_sh[1])[idx];
            float4 q2 = ((const float4*)wq_sh[2])[idx];
            float4 q3 = ((const float4*)wq_sh[3])[idx];
            float u0a[4] = {x0.x, x0.y, x0.z, x0.w};
            float u1a[4] = {x1.x, x1.y, x1.z, x1.w};
            float va[4]  = {vf.x, vf.y, vf.z, vf.w};
            float qa[4][4] = {{q0.x, q0.y, q0.z, q0.w},
                              {q1.x, q1.y, q1.z, q1.w},
                              {q2.x, q2.y, q2.z, q2.w},
                              {q3.x, q3.y, q3.z, q3.w}};
            #pragma unroll
            for (int cidx = 0; cidx < 4; cidx++) {
                const float vd = va[cidx];
                #pragma unroll
                for (int tt = 0; tt < 4; tt++) {
                    acc[0][tt] = fmaf(vd, fast_tanh(u0a[cidx] + qa[tt][cidx]), acc[0][tt]);
                    acc[1][tt] = fmaf(vd, fast_tanh(u1a[cidx] + qa[tt][cidx]), acc[1][tt]);
                }
            }
        }
        #pragma unroll
        for (int o = 16; o; o >>= 1) {
            #pragma unroll
            for (int p = 0; p < 2; p++)
                #pragma unroll
                for (int tt = 0; tt < 4; tt++)
                    acc[p][tt] += __shfl_xor_sync(0xFFFFFFFFu, acc[p][tt], o);
        }
        if (lane == 0) {
            #pragma unroll
            for (int tt = 0; tt < 4; tt++) {
                al_sh[tt][s]     = acc[0][tt];
                al_sh[tt][s + 1] = acc[1][tt];
            }
        }
    }
    __syncthreads();

    // ---- softmax over s: warp tt handles row t0+tt ----
    if (warp < 4) {
        float m = -1e30f;
        for (int s = lane; s < S_; s += 32) m = fmaxf(m, al_sh[warp][s]);
        #pragma unroll
        for (int o = 16; o; o >>= 1)
            m = fmaxf(m, __shfl_xor_sync(0xFFFFFFFFu, m, o));
        float sum = 0.f;
        for (int s = lane; s < S_; s += 32) {
            float e = __expf(al_sh[warp][s] - m);
            al_sh[warp][s] = e;
            sum += e;
        }
        #pragma unroll
        for (int o = 16; o; o >>= 1)
            sum += __shfl_xor_sync(0xFFFFFFFFu, sum, o);
        float inv = 1.0f / sum;
        float* aout = align_out + ((long)(b * T_ + t0 + warp)) * S_;
        for (int s = lane; s < S_; s += 32) {
            float p = al_sh[warp][s] * inv;
            al_sh[warp][s] = p;
            aout[s] = p;
        }
    }
    __syncthreads();

    // ---- context vectors: c[tt][d] = sum_s p[tt][s]*context[b,s,d]; d=tid ----
    const int d = tid;
    float c0 = 0.f, c1 = 0.f, c2 = 0.f, c3 = 0.f;
    const float* cptr = context + ((long)b * S_) * D_ + d;
    #pragma unroll 4
    for (int s = 0; s < S_; s++) {
        float cx = cptr[(long)s * D_];
        c0 = fmaf(al_sh[0][s], cx, c0);
        c1 = fmaf(al_sh[1][s], cx, c1);
        c2 = fmaf(al_sh[2][s], cx, c2);
        c3 = fmaf(al_sh[3][s], cx, c3);
    }
    c_out[((long)(b * T_ + t0 + 0)) * D_ + d] = c0;
    c_out[((long)(b * T_ + t0 + 1)) * D_ + d] = c1;
    c_out[((long)(b * T_ + t0 + 2)) * D_ + d] = c2;
    c_out[((long)(b * T_ + t0 + 3)) * D_ + d] = c3;
}

// ---------------------------------------------------------------------------
extern "C" void kernel_launch(void* const* d_in, const int* in_sizes, int n_in,
                              void* d_out, int out_size)
{
    const float* inp     = (const float*)d_in[0];
    const float* context = (const float*)d_in[1];
    const float* Wq      = (const float*)d_in[2];
    const float* bq      = (const float*)d_in[3];
    const float* Wc      = (const float*)d_in[4];
    const float* v       = (const float*)d_in[5];
    const float* Wout    = (const float*)d_in[6];
    const float* bout    = (const float*)d_in[7];

    float* out    = (float*)d_out;
    float* attn_h = out;                         // (B,T,D)
    float* align  = out + (long)B_ * T_ * D_;    // (B,T,S)

    float *p_wq, *p_uh, *p_pre, *p_c;
    cudaGetSymbolAddress((void**)&p_wq, g_wq);
    cudaGetSymbolAddress((void**)&p_uh, g_uh);
    cudaGetSymbolAddress((void**)&p_pre, g_pre);
    cudaGetSymbolAddress((void**)&p_c, g_c);

    // ---- Launch 1: fused {wq, uh, pre} GEMMs, all K=512 ----
    GemmArgs a1;
    // seg0: wq = inp @ Wq^T + bq             (M=512)
    a1.A[0] = inp;     a1.W[0] = Wq;          a1.bias[0] = bq;      a1.addC[0] = nullptr;
    a1.C[0] = p_wq;    a1.lda[0] = D_;        a1.ldw[0] = D_;       a1.ldc[0] = D_;
    // seg1: uh = context @ Wc^T              (M=2048)
    a1.A[1] = context; a1.W[1] = Wc;          a1.bias[1] = nullptr; a1.addC[1] = nullptr;
    a1.C[1] = p_uh;    a1.lda[1] = D_;        a1.ldw[1] = D_;       a1.ldc[1] = D_;
    // seg2: pre = inp @ WoutR^T + bout       (M=512, WoutR = Wout[:,512:])
    a1.A[2] = inp;     a1.W[2] = Wout + D_;   a1.bias[2] = bout;    a1.addC[2] = nullptr;
    a1.C[2] = p_pre;   a1.lda[2] = D_;        a1.ldw[2] = 2 * D_;   a1.ldc[2] = D_;
    a1.segEnd[0] = 8; a1.segEnd[1] = 40; a1.segEnd[2] = 48;
    gemm_seg_kernel<<<dim3(48, 8, 1), 256>>>(a1, D_);

    // ---- Launch 2: fused scores + softmax + context vectors ----
    attn_kernel<<<dim3(T_ / 4, B_), 512>>>(p_wq, p_uh, v, context, align, p_c);

    // ---- Launch 3: attn_h = c @ WoutL^T + pre  (full K, epilogue fold) ----
    GemmArgs a3;
    a3.A[0] = p_c;  a3.W[0] = Wout;  a3.bias[0] = nullptr;  a3.addC[0] = p_pre;
    a3.C[0] = attn_h;
    a3.lda[0] = D_; a3.ldw[0] = 2 * D_; a3.ldc[0] = D_;
    a3.A[1] = a3.A[0]; a3.W[1] = a3.W[0]; a3.bias[1] = nullptr; a3.addC[1] = nullptr;
    a3.C[1] = a3.C[0]; a3.lda[1] = a3.lda[0]; a3.ldw[1] = a3.ldw[0]; a3.ldc[1] = a3.ldc[0];
    a3.A[2] = a3.A[0]; a3.W[2] = a3.W[0]; a3.bias[2] = nullptr; a3.addC[2] = nullptr;
    a3.C[2] = a3.C[0]; a3.lda[2] = a3.lda[0]; a3.ldw[2] = a3.ldw[0]; a3.ldc[2] = a3.ldc[0];
    a3.segEnd[0] = 8; a3.segEnd[1] = 8; a3.segEnd[2] = 8;
    gemm_seg_kernel<<<dim3(8, 8, 1), 256>>>(a3, D_);
}